// round 2
// baseline (speedup 1.0000x reference)
#include <cuda_runtime.h>
#include <cuda_bf16.h>
#include <math.h>

// ---------------- problem constants ----------------
#define BB     4
#define TC     4
#define CIN    1024
#define FFD    512
#define OUTD   128
#define NCTX   1024            // TC*16*16
#define NTOT   4096            // BB*NCTX
#define KCONV  27648           // CIN*27
#define PCONV  1568            // BB*2*14*14
#define KSPLIT 8
#define KCHUNK 3456            // KCONV/KSPLIT
#define BT     24              // BB*6 frames
#define NS     1024            // 32*32 upsampled positions

// ---------------- scratch (device globals; no allocation allowed) ----------------
__device__ float g_x[(size_t)CIN * NTOT];        // 16.8 MB  activations [c][b*1024+t*256+hw]
__device__ float g_y[(size_t)CIN * NTOT];        // 16.8 MB
__device__ float g_v[(size_t)FFD * NTOT];        // 8.4 MB
__device__ float g_col[(size_t)KCONV * PCONV];   // 173 MB im2col
__device__ float g_conv[(size_t)FFD * PCONV];    // conv3d out [f][p]
__device__ float g_gp[BB * FFD];                 // goal_pre
__device__ float g_fb[(size_t)CIN * (BT * 64)];  // frame transposed [c][bt*64+hw]
__device__ float g_w1t[4 * FFD * CIN];           // up1 weights [kl][o][c]
__device__ float g_w2t[4 * FFD * FFD];           // up2 weights [kl][o][c]
__device__ float g_s1[(size_t)FFD * (BT * 256)]; // up1 out [o][bt*256+hw16]
__device__ float g_s2[(size_t)FFD * (BT * 1024)];// up2 out [o][bt*1024+hw32]
__device__ float g_attn[BT * NS];
__device__ float g_sga[BT * FFD];

// ---------------- generic tiled FP32 GEMM: C[M,N] = A[M,K] @ B[K,N] ----------------
// MODE 0: plain store
// MODE 1: C = xin + relu(acc + bias[row])          (nonlocal residual)
// MODE 2: atomicAdd into C                          (conv K-split)
// MODE 3: up1 scatter: relu(acc+bias) -> s1 strided
// MODE 4: up2 scatter: acc+bias       -> s2 strided
template <int MODE>
__global__ void sgemm(const float* __restrict__ A, int lda,
                      const float* __restrict__ Bm, int ldb,
                      float* __restrict__ Cm,
                      int M, int N, int K,
                      const float* __restrict__ bias,
                      const float* __restrict__ xin,
                      int kk, int ll)
{
    // K-split (gridDim.z > 1): advance both operands
    A  += (size_t)blockIdx.z * K;
    Bm += (size_t)blockIdx.z * K * (size_t)ldb;

    __shared__ float As[8][128];
    __shared__ float Bs[8][128];
    const int tid  = threadIdx.x;
    const int row0 = blockIdx.y * 128;
    const int col0 = blockIdx.x * 128;

    const int a_r = tid >> 1;            // 0..127
    const int a_c = (tid & 1) * 4;       // 0,4
    const int b_r = tid >> 5;            // 0..7
    const int b_c = (tid & 31) * 4;      // 0..124
    const int tx  = (tid & 15) * 8;
    const int ty  = (tid >> 4) * 8;

    float acc[8][8];
#pragma unroll
    for (int i = 0; i < 8; i++)
#pragma unroll
        for (int j = 0; j < 8; j++) acc[i][j] = 0.f;

    for (int k0 = 0; k0 < K; k0 += 8) {
        float4 av = *reinterpret_cast<const float4*>(&A[(size_t)(row0 + a_r) * lda + k0 + a_c]);
        As[a_c + 0][a_r] = av.x; As[a_c + 1][a_r] = av.y;
        As[a_c + 2][a_r] = av.z; As[a_c + 3][a_r] = av.w;

        int gcol = col0 + b_c;
        float4 bv;
        if (gcol + 3 < N) {
            bv = *reinterpret_cast<const float4*>(&Bm[(size_t)(k0 + b_r) * ldb + gcol]);
        } else {
            bv.x = (gcol + 0 < N) ? Bm[(size_t)(k0 + b_r) * ldb + gcol + 0] : 0.f;
            bv.y = (gcol + 1 < N) ? Bm[(size_t)(k0 + b_r) * ldb + gcol + 1] : 0.f;
            bv.z = (gcol + 2 < N) ? Bm[(size_t)(k0 + b_r) * ldb + gcol + 2] : 0.f;
            bv.w = (gcol + 3 < N) ? Bm[(size_t)(k0 + b_r) * ldb + gcol + 3] : 0.f;
        }
        *reinterpret_cast<float4*>(&Bs[b_r][b_c]) = bv;
        __syncthreads();

#pragma unroll
        for (int k = 0; k < 8; k++) {
            float ra[8], rb[8];
#pragma unroll
            for (int i = 0; i < 8; i++) ra[i] = As[k][ty + i];
#pragma unroll
            for (int j = 0; j < 8; j++) rb[j] = Bs[k][tx + j];
#pragma unroll
            for (int i = 0; i < 8; i++)
#pragma unroll
                for (int j = 0; j < 8; j++) acc[i][j] += ra[i] * rb[j];
        }
        __syncthreads();
    }

#pragma unroll
    for (int i = 0; i < 8; i++) {
        const int row = row0 + ty + i;
        float bi = 0.f;
        if (MODE == 1 || MODE == 3 || MODE == 4) bi = bias[row];
#pragma unroll
        for (int j = 0; j < 8; j++) {
            const int col = col0 + tx + j;
            if (col >= N) continue;
            float v = acc[i][j];
            if (MODE == 0) {
                Cm[(size_t)row * N + col] = v;
            } else if (MODE == 1) {
                v = fmaxf(v + bi, 0.f);
                Cm[(size_t)row * N + col] = xin[(size_t)row * N + col] + v;
            } else if (MODE == 2) {
                atomicAdd(&Cm[(size_t)row * N + col], v);
            } else if (MODE == 3) {
                int bt = col >> 6, r = col & 63, h = r >> 3, w = r & 7;
                int oc = bt * 256 + (h * 2 + kk) * 16 + (w * 2 + ll);
                Cm[(size_t)row * (BT * 256) + oc] = fmaxf(v + bi, 0.f);
            } else { // MODE 4
                int bt = col >> 8, r = col & 255, h = r >> 4, w = r & 15;
                int oc = bt * 1024 + (h * 2 + kk) * 32 + (w * 2 + ll);
                Cm[(size_t)row * (BT * 1024) + oc] = v + bi;
            }
        }
    }
}

// ---------------- misc kernels ----------------
__global__ void transpose_ctx(const float* __restrict__ ctx) {
    int idx = blockIdx.x * blockDim.x + threadIdx.x;   // c*4096 + bt*256 + hw
    int c  = idx >> 12;
    int r  = idx & 4095;
    int bt = r >> 8;          // b*4 + t
    int hw = r & 255;
    g_x[idx] = ctx[((size_t)bt * CIN + c) * 256 + hw];
}

__global__ void bn_kernel(const float* __restrict__ y, float* __restrict__ xo,
                          const float* __restrict__ gamma, const float* __restrict__ beta) {
    int c = blockIdx.x, tid = threadIdx.x;
    const float* row = y + (size_t)c * NTOT;
    float s = 0.f, q = 0.f;
    for (int j = tid; j < NTOT; j += 256) { float t = row[j]; s += t; q += t * t; }
    __shared__ float ss[256], qq[256];
    ss[tid] = s; qq[tid] = q; __syncthreads();
    for (int o = 128; o > 0; o >>= 1) {
        if (tid < o) { ss[tid] += ss[tid + o]; qq[tid] += qq[tid + o]; }
        __syncthreads();
    }
    __shared__ float sm, sinv;
    if (tid == 0) {
        float m = ss[0] * (1.f / NTOT);
        float var = qq[0] * (1.f / NTOT) - m * m;
        sm = m; sinv = rsqrtf(var + 1e-5f);
    }
    __syncthreads();
    float m = sm, inv = sinv, g = gamma[c], b = beta[c];
    float* o = xo + (size_t)c * NTOT;
    for (int j = tid; j < NTOT; j += 256) o[j] = (row[j] - m) * inv * g + b;
}

__global__ void im2col_kernel() {
    int idx = blockIdx.x * blockDim.x + threadIdx.x;   // k*1568 + p
    int k = idx / PCONV, p = idx % PCONV;
    int c = k / 27, r = k % 27;
    int dt = r / 9, dh = (r / 3) % 3, dw = r % 3;
    int b = p / 392, q = p % 392;
    int t = q / 196, rem = q % 196, h = rem / 14, w = rem % 14;
    g_col[idx] = g_x[(size_t)c * NTOT + (b * 4 + t + dt) * 256 + (h + dh) * 16 + (w + dw)];
}

__global__ void zero_kernel(float* p, int n) {
    int i = blockIdx.x * blockDim.x + threadIdx.x;
    if (i < n) p[i] = 0.f;
}

__global__ void goalpre_kernel(const float* __restrict__ tb) {
    int f = blockIdx.x, b = blockIdx.y, tid = threadIdx.x;  // 128 threads
    const float* p = g_conv + (size_t)f * PCONV + b * 392;
    float bias = tb[f];
    float s = 0.f;
    for (int i = tid; i < 392; i += 128) s += fmaxf(p[i] + bias, 0.f);
    __shared__ float red[128];
    red[tid] = s; __syncthreads();
    for (int o = 64; o > 0; o >>= 1) { if (tid < o) red[tid] += red[tid + o]; __syncthreads(); }
    if (tid == 0) g_gp[b * FFD + f] = red[0] * (1.f / 392.f);
}

__global__ void pack_frame(const float* __restrict__ fr) {
    int idx = blockIdx.x * blockDim.x + threadIdx.x;   // c*1536 + bt*64 + hw
    int c = idx / (BT * 64);
    int r = idx % (BT * 64);
    int bt = r >> 6, hw = r & 63;
    g_fb[idx] = fr[((size_t)bt * CIN + c) * 64 + hw];
}

__global__ void pack_w1(const float* __restrict__ w) {
    int idx = blockIdx.x * blockDim.x + threadIdx.x;   // kl*524288 + o*1024 + c
    int kl = idx >> 19;
    int o = (idx >> 10) & 511;
    int c = idx & 1023;
    g_w1t[idx] = w[((size_t)c * FFD + o) * 4 + kl];
}

__global__ void pack_w2(const float* __restrict__ w) {
    int idx = blockIdx.x * blockDim.x + threadIdx.x;   // kl*262144 + o*512 + c
    int kl = idx >> 18;
    int o = (idx >> 9) & 511;
    int c = idx & 511;
    g_w2t[idx] = w[((size_t)c * FFD + o) * 4 + kl];
}

__global__ void sg_softmax_kernel() {
    int bt = blockIdx.x, tid = threadIdx.x;   // 256 threads
    int b = bt / 6;
    __shared__ float g[512];
    g[tid] = g_gp[b * FFD + tid];
    g[tid + 256] = g_gp[b * FFD + tid + 256];
    __syncthreads();
    const float* base = g_s2 + bt * 1024;
    float v[4];
#pragma unroll
    for (int i = 0; i < 4; i++) {
        int n = tid + i * 256;
        float s = 0.f;
        for (int c = 0; c < FFD; c++) s += base[(size_t)c * (BT * 1024) + n] * g[c];
        v[i] = s;
    }
    __shared__ float red[256];
    float m = fmaxf(fmaxf(v[0], v[1]), fmaxf(v[2], v[3]));
    red[tid] = m; __syncthreads();
    for (int o = 128; o > 0; o >>= 1) { if (tid < o) red[tid] = fmaxf(red[tid], red[tid + o]); __syncthreads(); }
    m = red[0]; __syncthreads();
    float s = 0.f;
#pragma unroll
    for (int i = 0; i < 4; i++) { v[i] = expf(v[i] - m); s += v[i]; }
    red[tid] = s; __syncthreads();
    for (int o = 128; o > 0; o >>= 1) { if (tid < o) red[tid] += red[tid + o]; __syncthreads(); }
    float inv = 1.f / red[0];
#pragma unroll
    for (int i = 0; i < 4; i++) g_attn[bt * 1024 + tid + i * 256] = v[i] * inv;
}

__global__ void sga_kernel() {
    int bt = blockIdx.x;
    int c = blockIdx.y * 8 + (threadIdx.x >> 5);
    int lane = threadIdx.x & 31;
    int i2 = (c >> 1) * 2;
    float div = expf(-0.01798894603890390f * (float)i2);  // ln(10000)/512
    const float* p = g_s2 + (size_t)c * (BT * 1024) + bt * 1024;
    const float* a = g_attn + bt * 1024;
    float acc = 0.f;
    for (int n = lane; n < 1024; n += 32) {
        float ang = (float)n * div;
        float pe = (c & 1) ? cosf(ang) : sinf(ang);
        acc += a[n] * (p[n] + pe);
    }
    for (int o = 16; o > 0; o >>= 1) acc += __shfl_down_sync(0xffffffffu, acc, o);
    if (lane == 0) g_sga[bt * FFD + c] = acc;
}

// MLP head: out[r] = relu(in[r] @ W1^T + b1) @ W2^T + b2
__global__ void head_kernel(const float* __restrict__ in,
                            const float* __restrict__ W1, const float* __restrict__ b1,
                            const float* __restrict__ W2, const float* __restrict__ b2,
                            float* __restrict__ out) {
    int r = blockIdx.x, j = threadIdx.x;   // 512 threads
    __shared__ float xin[512];
    xin[j] = in[r * FFD + j];
    __syncthreads();
    float acc = b1[j];
    const float* w = W1 + (size_t)j * FFD;
    for (int k = 0; k < FFD; k++) acc += xin[k] * w[k];
    __shared__ float t[512];
    t[j] = fmaxf(acc, 0.f);
    __syncthreads();
    if (j < OUTD) {
        float a2 = b2[j];
        const float* w2 = W2 + (size_t)j * FFD;
        for (int k = 0; k < FFD; k++) a2 += t[k] * w2[k];
        out[r * OUTD + j] = a2;
    }
}

// ---------------- launch ----------------
extern "C" void kernel_launch(void* const* d_in, const int* in_sizes, int n_in,
                              void* d_out, int out_size) {
    const float* ctx   = (const float*)d_in[0];
    const float* frame = (const float*)d_in[1];
    const float* nl_vw[2]   = { (const float*)d_in[4],  (const float*)d_in[11] };
    const float* nl_ow[2]   = { (const float*)d_in[5],  (const float*)d_in[12] };
    const float* nl_ob[2]   = { (const float*)d_in[6],  (const float*)d_in[13] };
    const float* nl_g[2]    = { (const float*)d_in[7],  (const float*)d_in[14] };
    const float* nl_beta[2] = { (const float*)d_in[8],  (const float*)d_in[15] };
    const float* tp_w  = (const float*)d_in[16];
    const float* tp_b  = (const float*)d_in[17];
    const float* up1_w = (const float*)d_in[18];
    const float* up1_b = (const float*)d_in[19];
    const float* up2_w = (const float*)d_in[20];
    const float* up2_b = (const float*)d_in[21];
    const float* og1_w = (const float*)d_in[22];
    const float* og1_b = (const float*)d_in[23];
    const float* og2_w = (const float*)d_in[24];
    const float* og2_b = (const float*)d_in[25];
    const float* os1_w = (const float*)d_in[26];
    const float* os1_b = (const float*)d_in[27];
    const float* os2_w = (const float*)d_in[28];
    const float* os2_b = (const float*)d_in[29];
    float* out = (float*)d_out;

    float *px, *py, *pv, *pconv, *pw1t, *pw2t, *ps1, *ps2, *pfb, *pcol, *pgp, *psga;
    cudaGetSymbolAddress((void**)&px, g_x);
    cudaGetSymbolAddress((void**)&py, g_y);
    cudaGetSymbolAddress((void**)&pv, g_v);
    cudaGetSymbolAddress((void**)&pconv, g_conv);
    cudaGetSymbolAddress((void**)&pw1t, g_w1t);
    cudaGetSymbolAddress((void**)&pw2t, g_w2t);
    cudaGetSymbolAddress((void**)&ps1, g_s1);
    cudaGetSymbolAddress((void**)&ps2, g_s2);
    cudaGetSymbolAddress((void**)&pfb, g_fb);
    cudaGetSymbolAddress((void**)&pcol, g_col);
    cudaGetSymbolAddress((void**)&pgp, g_gp);
    cudaGetSymbolAddress((void**)&psga, g_sga);

    // 1) context -> [c][b,t,hw]
    transpose_ctx<<<(CIN * NTOT) / 256, 256>>>(ctx);

    // 2) two nonlocal layers (attention collapses: y = x + relu(ow@(vw@x)+ob), then BN)
    for (int l = 0; l < 2; l++) {
        sgemm<0><<<dim3(NTOT / 128, FFD / 128, 1), 256>>>(
            nl_vw[l], CIN, px, NTOT, pv, FFD, NTOT, CIN, nullptr, nullptr, 0, 0);
        sgemm<1><<<dim3(NTOT / 128, CIN / 128, 1), 256>>>(
            nl_ow[l], FFD, pv, NTOT, py, CIN, NTOT, FFD, nl_ob[l], px, 0, 0);
        bn_kernel<<<CIN, 256>>>(py, px, nl_g[l], nl_beta[l]);
    }

    // 3) conv3d (im2col + K-split GEMM) -> relu -> mean = goal_pre
    im2col_kernel<<<(int)(((size_t)KCONV * PCONV) / 256), 256>>>();
    zero_kernel<<<(FFD * PCONV + 255) / 256, 256>>>(pconv, FFD * PCONV);
    sgemm<2><<<dim3((PCONV + 127) / 128, FFD / 128, KSPLIT), 256>>>(
        tp_w, KCONV, pcol, PCONV, pconv, FFD, PCONV, KCHUNK, nullptr, nullptr, 0, 0);
    goalpre_kernel<<<dim3(FFD, BB), 128>>>(tp_b);

    // 4) ConvTranspose chain
    pack_frame<<<(CIN * BT * 64) / 256, 256>>>(frame);
    pack_w1<<<(4 * FFD * CIN) / 256, 256>>>(up1_w);
    pack_w2<<<(4 * FFD * FFD) / 256, 256>>>(up2_w);
    for (int kl = 0; kl < 4; kl++) {
        int k = kl >> 1, lcol = kl & 1;
        sgemm<3><<<dim3((BT * 64) / 128, FFD / 128, 1), 256>>>(
            pw1t + (size_t)kl * FFD * CIN, CIN, pfb, BT * 64, ps1, FFD, BT * 64, CIN,
            up1_b, nullptr, k, lcol);
    }
    for (int kl = 0; kl < 4; kl++) {
        int k = kl >> 1, lcol = kl & 1;
        sgemm<4><<<dim3((BT * 256) / 128, FFD / 128, 1), 256>>>(
            pw2t + (size_t)kl * FFD * FFD, FFD, ps1, BT * 256, ps2, FFD, BT * 256, FFD,
            up2_b, nullptr, k, lcol);
    }

    // 5) spatial attention over upsampled features
    sg_softmax_kernel<<<BT, 256>>>();
    sga_kernel<<<dim3(BT, FFD / 8), 256>>>();

    // 6) heads: goal [4,128] then state [24,128]
    head_kernel<<<BB, 512>>>(pgp, og1_w, og1_b, og2_w, og2_b, out);
    head_kernel<<<BT, 512>>>(psga, os1_w, os1_b, os2_w, os2_b, out + BB * OUTD);
}

// round 3
// speedup vs baseline: 1.0023x; 1.0023x over previous
#include <cuda_runtime.h>
#include <cuda_bf16.h>
#include <math.h>

// ---------------- problem constants ----------------
#define BB     4
#define TC     4
#define CIN    1024
#define FFD    512
#define OUTD   128
#define NCTX   1024            // TC*16*16
#define NTOT   4096            // BB*NCTX
#define KCONV  27648           // CIN*27
#define PCONV  1568            // BB*2*14*14
#define KSPLIT 8
#define KCHUNK 3456            // KCONV/KSPLIT
#define BT     24              // BB*6 frames
#define NS     1024            // 32*32 upsampled positions

// ---------------- scratch (device globals; no allocation allowed) ----------------
__device__ float g_x[(size_t)CIN * NTOT];        // 16.8 MB  activations [c][b*1024+t*256+hw]
__device__ float g_y[(size_t)CIN * NTOT];        // 16.8 MB
__device__ float g_v[(size_t)FFD * NTOT];        // 8.4 MB
__device__ float g_col[(size_t)KCONV * PCONV];   // 173 MB im2col
__device__ float g_conv[(size_t)FFD * PCONV];    // conv3d out [f][p]
__device__ float g_gp[BB * FFD];                 // goal_pre
__device__ float g_fb[(size_t)CIN * (BT * 64)];  // frame transposed [c][bt*64+hw]
__device__ float g_w1t[4 * FFD * CIN];           // up1 weights [kl][o][c]
__device__ float g_w2t[4 * FFD * FFD];           // up2 weights [kl][o][c]
__device__ float g_s1[(size_t)FFD * (BT * 256)]; // up1 out [o][bt*256+hw16]
__device__ float g_s2[(size_t)FFD * (BT * 1024)];// up2 out [o][bt*1024+hw32]
__device__ float g_attn[BT * NS];
__device__ float g_sga[BT * FFD];

// ---------------- generic tiled FP32 GEMM: C[M,N] = A[M,K] @ B[K,N] ----------------
// MODE 0: plain store
// MODE 1: C = xin + relu(acc + bias[row])          (nonlocal residual)
// MODE 2: atomicAdd into C                          (conv K-split)
// MODE 3: up1 scatter: relu(acc+bias) -> s1 strided
// MODE 4: up2 scatter: acc+bias       -> s2 strided
template <int MODE>
__global__ void sgemm(const float* __restrict__ A, int lda,
                      const float* __restrict__ Bm, int ldb,
                      float* __restrict__ Cm,
                      int M, int N, int K,
                      const float* __restrict__ bias,
                      const float* __restrict__ xin,
                      int kk, int ll)
{
    // K-split (gridDim.z > 1): advance both operands
    A  += (size_t)blockIdx.z * K;
    Bm += (size_t)blockIdx.z * K * (size_t)ldb;

    __shared__ float As[8][128];
    __shared__ float Bs[8][128];
    const int tid  = threadIdx.x;
    const int row0 = blockIdx.y * 128;
    const int col0 = blockIdx.x * 128;

    const int a_r = tid >> 1;            // 0..127
    const int a_c = (tid & 1) * 4;       // 0,4
    const int b_r = tid >> 5;            // 0..7
    const int b_c = (tid & 31) * 4;      // 0..124
    const int tx  = (tid & 15) * 8;
    const int ty  = (tid >> 4) * 8;

    float acc[8][8];
#pragma unroll
    for (int i = 0; i < 8; i++)
#pragma unroll
        for (int j = 0; j < 8; j++) acc[i][j] = 0.f;

    for (int k0 = 0; k0 < K; k0 += 8) {
        float4 av = *reinterpret_cast<const float4*>(&A[(size_t)(row0 + a_r) * lda + k0 + a_c]);
        As[a_c + 0][a_r] = av.x; As[a_c + 1][a_r] = av.y;
        As[a_c + 2][a_r] = av.z; As[a_c + 3][a_r] = av.w;

        int gcol = col0 + b_c;
        float4 bv;
        if (gcol + 3 < N) {
            bv = *reinterpret_cast<const float4*>(&Bm[(size_t)(k0 + b_r) * ldb + gcol]);
        } else {
            bv.x = (gcol + 0 < N) ? Bm[(size_t)(k0 + b_r) * ldb + gcol + 0] : 0.f;
            bv.y = (gcol + 1 < N) ? Bm[(size_t)(k0 + b_r) * ldb + gcol + 1] : 0.f;
            bv.z = (gcol + 2 < N) ? Bm[(size_t)(k0 + b_r) * ldb + gcol + 2] : 0.f;
            bv.w = (gcol + 3 < N) ? Bm[(size_t)(k0 + b_r) * ldb + gcol + 3] : 0.f;
        }
        *reinterpret_cast<float4*>(&Bs[b_r][b_c]) = bv;
        __syncthreads();

#pragma unroll
        for (int k = 0; k < 8; k++) {
            float ra[8], rb[8];
#pragma unroll
            for (int i = 0; i < 8; i++) ra[i] = As[k][ty + i];
#pragma unroll
            for (int j = 0; j < 8; j++) rb[j] = Bs[k][tx + j];
#pragma unroll
            for (int i = 0; i < 8; i++)
#pragma unroll
                for (int j = 0; j < 8; j++) acc[i][j] += ra[i] * rb[j];
        }
        __syncthreads();
    }

#pragma unroll
    for (int i = 0; i < 8; i++) {
        const int row = row0 + ty + i;
        float bi = 0.f;
        if (MODE == 1 || MODE == 3 || MODE == 4) bi = bias[row];
#pragma unroll
        for (int j = 0; j < 8; j++) {
            const int col = col0 + tx + j;
            if (col >= N) continue;
            float v = acc[i][j];
            if (MODE == 0) {
                Cm[(size_t)row * N + col] = v;
            } else if (MODE == 1) {
                v = fmaxf(v + bi, 0.f);
                Cm[(size_t)row * N + col] = xin[(size_t)row * N + col] + v;
            } else if (MODE == 2) {
                atomicAdd(&Cm[(size_t)row * N + col], v);
            } else if (MODE == 3) {
                int bt = col >> 6, r = col & 63, h = r >> 3, w = r & 7;
                int oc = bt * 256 + (h * 2 + kk) * 16 + (w * 2 + ll);
                Cm[(size_t)row * (BT * 256) + oc] = fmaxf(v + bi, 0.f);
            } else { // MODE 4
                int bt = col >> 8, r = col & 255, h = r >> 4, w = r & 15;
                int oc = bt * 1024 + (h * 2 + kk) * 32 + (w * 2 + ll);
                Cm[(size_t)row * (BT * 1024) + oc] = v + bi;
            }
        }
    }
}

// ---------------- misc kernels ----------------
__global__ void transpose_ctx(const float* __restrict__ ctx) {
    int idx = blockIdx.x * blockDim.x + threadIdx.x;   // c*4096 + bt*256 + hw
    int c  = idx >> 12;
    int r  = idx & 4095;
    int bt = r >> 8;          // b*4 + t
    int hw = r & 255;
    g_x[idx] = ctx[((size_t)bt * CIN + c) * 256 + hw];
}

__global__ void bn_kernel(const float* __restrict__ y, float* __restrict__ xo,
                          const float* __restrict__ gamma, const float* __restrict__ beta) {
    int c = blockIdx.x, tid = threadIdx.x;
    const float* row = y + (size_t)c * NTOT;
    float s = 0.f, q = 0.f;
    for (int j = tid; j < NTOT; j += 256) { float t = row[j]; s += t; q += t * t; }
    __shared__ float ss[256], qq[256];
    ss[tid] = s; qq[tid] = q; __syncthreads();
    for (int o = 128; o > 0; o >>= 1) {
        if (tid < o) { ss[tid] += ss[tid + o]; qq[tid] += qq[tid + o]; }
        __syncthreads();
    }
    __shared__ float sm, sinv;
    if (tid == 0) {
        float m = ss[0] * (1.f / NTOT);
        float var = qq[0] * (1.f / NTOT) - m * m;
        sm = m; sinv = rsqrtf(var + 1e-5f);
    }
    __syncthreads();
    float m = sm, inv = sinv, g = gamma[c], b = beta[c];
    float* o = xo + (size_t)c * NTOT;
    for (int j = tid; j < NTOT; j += 256) o[j] = (row[j] - m) * inv * g + b;
}

__global__ void im2col_kernel() {
    int idx = blockIdx.x * blockDim.x + threadIdx.x;   // k*1568 + p
    int k = idx / PCONV, p = idx % PCONV;
    int c = k / 27, r = k % 27;
    int dt = r / 9, dh = (r / 3) % 3, dw = r % 3;
    int b = p / 392, q = p % 392;
    int t = q / 196, rem = q % 196, h = rem / 14, w = rem % 14;
    g_col[idx] = g_x[(size_t)c * NTOT + (b * 4 + t + dt) * 256 + (h + dh) * 16 + (w + dw)];
}

__global__ void zero_kernel(float* p, int n) {
    int i = blockIdx.x * blockDim.x + threadIdx.x;
    if (i < n) p[i] = 0.f;
}

__global__ void goalpre_kernel(const float* __restrict__ tb) {
    int f = blockIdx.x, b = blockIdx.y, tid = threadIdx.x;  // 128 threads
    const float* p = g_conv + (size_t)f * PCONV + b * 392;
    float bias = tb[f];
    float s = 0.f;
    for (int i = tid; i < 392; i += 128) s += fmaxf(p[i] + bias, 0.f);
    __shared__ float red[128];
    red[tid] = s; __syncthreads();
    for (int o = 64; o > 0; o >>= 1) { if (tid < o) red[tid] += red[tid + o]; __syncthreads(); }
    if (tid == 0) g_gp[b * FFD + f] = red[0] * (1.f / 392.f);
}

__global__ void pack_frame(const float* __restrict__ fr) {
    int idx = blockIdx.x * blockDim.x + threadIdx.x;   // c*1536 + bt*64 + hw
    int c = idx / (BT * 64);
    int r = idx % (BT * 64);
    int bt = r >> 6, hw = r & 63;
    g_fb[idx] = fr[((size_t)bt * CIN + c) * 64 + hw];
}

__global__ void pack_w1(const float* __restrict__ w) {
    int idx = blockIdx.x * blockDim.x + threadIdx.x;   // kl*524288 + o*1024 + c
    int kl = idx >> 19;
    int o = (idx >> 10) & 511;
    int c = idx & 1023;
    g_w1t[idx] = w[((size_t)c * FFD + o) * 4 + kl];
}

__global__ void pack_w2(const float* __restrict__ w) {
    int idx = blockIdx.x * blockDim.x + threadIdx.x;   // kl*262144 + o*512 + c
    int kl = idx >> 18;
    int o = (idx >> 9) & 511;
    int c = idx & 511;
    g_w2t[idx] = w[((size_t)c * FFD + o) * 4 + kl];
}

__global__ void sg_softmax_kernel() {
    int bt = blockIdx.x, tid = threadIdx.x;   // 256 threads
    int b = bt / 6;
    __shared__ float g[512];
    g[tid] = g_gp[b * FFD + tid];
    g[tid + 256] = g_gp[b * FFD + tid + 256];
    __syncthreads();
    const float* base = g_s2 + bt * 1024;
    float v[4];
#pragma unroll
    for (int i = 0; i < 4; i++) {
        int n = tid + i * 256;
        float s = 0.f;
        for (int c = 0; c < FFD; c++) s += base[(size_t)c * (BT * 1024) + n] * g[c];
        v[i] = s;
    }
    __shared__ float red[256];
    float m = fmaxf(fmaxf(v[0], v[1]), fmaxf(v[2], v[3]));
    red[tid] = m; __syncthreads();
    for (int o = 128; o > 0; o >>= 1) { if (tid < o) red[tid] = fmaxf(red[tid], red[tid + o]); __syncthreads(); }
    m = red[0]; __syncthreads();
    float s = 0.f;
#pragma unroll
    for (int i = 0; i < 4; i++) { v[i] = expf(v[i] - m); s += v[i]; }
    red[tid] = s; __syncthreads();
    for (int o = 128; o > 0; o >>= 1) { if (tid < o) red[tid] += red[tid + o]; __syncthreads(); }
    float inv = 1.f / red[0];
#pragma unroll
    for (int i = 0; i < 4; i++) g_attn[bt * 1024 + tid + i * 256] = v[i] * inv;
}

__global__ void sga_kernel() {
    int bt = blockIdx.x;
    int c = blockIdx.y * 8 + (threadIdx.x >> 5);
    int lane = threadIdx.x & 31;
    int i2 = (c >> 1) * 2;
    float div = expf(-0.01798894603890390f * (float)i2);  // ln(10000)/512
    const float* p = g_s2 + (size_t)c * (BT * 1024) + bt * 1024;
    const float* a = g_attn + bt * 1024;
    float acc = 0.f;
    for (int n = lane; n < 1024; n += 32) {
        float ang = (float)n * div;
        float pe = (c & 1) ? cosf(ang) : sinf(ang);
        acc += a[n] * (p[n] + pe);
    }
    for (int o = 16; o > 0; o >>= 1) acc += __shfl_down_sync(0xffffffffu, acc, o);
    if (lane == 0) g_sga[bt * FFD + c] = acc;
}

// MLP head: out[r] = relu(in[r] @ W1^T + b1) @ W2^T + b2
__global__ void head_kernel(const float* __restrict__ in,
                            const float* __restrict__ W1, const float* __restrict__ b1,
                            const float* __restrict__ W2, const float* __restrict__ b2,
                            float* __restrict__ out) {
    int r = blockIdx.x, j = threadIdx.x;   // 512 threads
    __shared__ float xin[512];
    xin[j] = in[r * FFD + j];
    __syncthreads();
    float acc = b1[j];
    const float* w = W1 + (size_t)j * FFD;
    for (int k = 0; k < FFD; k++) acc += xin[k] * w[k];
    __shared__ float t[512];
    t[j] = fmaxf(acc, 0.f);
    __syncthreads();
    if (j < OUTD) {
        float a2 = b2[j];
        const float* w2 = W2 + (size_t)j * FFD;
        for (int k = 0; k < FFD; k++) a2 += t[k] * w2[k];
        out[r * OUTD + j] = a2;
    }
}

// ---------------- launch ----------------
extern "C" void kernel_launch(void* const* d_in, const int* in_sizes, int n_in,
                              void* d_out, int out_size) {
    const float* ctx   = (const float*)d_in[0];
    const float* frame = (const float*)d_in[1];
    const float* nl_vw[2]   = { (const float*)d_in[4],  (const float*)d_in[11] };
    const float* nl_ow[2]   = { (const float*)d_in[5],  (const float*)d_in[12] };
    const float* nl_ob[2]   = { (const float*)d_in[6],  (const float*)d_in[13] };
    const float* nl_g[2]    = { (const float*)d_in[7],  (const float*)d_in[14] };
    const float* nl_beta[2] = { (const float*)d_in[8],  (const float*)d_in[15] };
    const float* tp_w  = (const float*)d_in[16];
    const float* tp_b  = (const float*)d_in[17];
    const float* up1_w = (const float*)d_in[18];
    const float* up1_b = (const float*)d_in[19];
    const float* up2_w = (const float*)d_in[20];
    const float* up2_b = (const float*)d_in[21];
    const float* og1_w = (const float*)d_in[22];
    const float* og1_b = (const float*)d_in[23];
    const float* og2_w = (const float*)d_in[24];
    const float* og2_b = (const float*)d_in[25];
    const float* os1_w = (const float*)d_in[26];
    const float* os1_b = (const float*)d_in[27];
    const float* os2_w = (const float*)d_in[28];
    const float* os2_b = (const float*)d_in[29];
    float* out = (float*)d_out;

    float *px, *py, *pv, *pconv, *pw1t, *pw2t, *ps1, *ps2, *pfb, *pcol, *pgp, *psga;
    cudaGetSymbolAddress((void**)&px, g_x);
    cudaGetSymbolAddress((void**)&py, g_y);
    cudaGetSymbolAddress((void**)&pv, g_v);
    cudaGetSymbolAddress((void**)&pconv, g_conv);
    cudaGetSymbolAddress((void**)&pw1t, g_w1t);
    cudaGetSymbolAddress((void**)&pw2t, g_w2t);
    cudaGetSymbolAddress((void**)&ps1, g_s1);
    cudaGetSymbolAddress((void**)&ps2, g_s2);
    cudaGetSymbolAddress((void**)&pfb, g_fb);
    cudaGetSymbolAddress((void**)&pcol, g_col);
    cudaGetSymbolAddress((void**)&pgp, g_gp);
    cudaGetSymbolAddress((void**)&psga, g_sga);

    // 1) context -> [c][b,t,hw]
    transpose_ctx<<<(CIN * NTOT) / 256, 256>>>(ctx);

    // 2) two nonlocal layers (attention collapses: y = x + relu(ow@(vw@x)+ob), then BN)
    for (int l = 0; l < 2; l++) {
        sgemm<0><<<dim3(NTOT / 128, FFD / 128, 1), 256>>>(
            nl_vw[l], CIN, px, NTOT, pv, FFD, NTOT, CIN, nullptr, nullptr, 0, 0);
        sgemm<1><<<dim3(NTOT / 128, CIN / 128, 1), 256>>>(
            nl_ow[l], FFD, pv, NTOT, py, CIN, NTOT, FFD, nl_ob[l], px, 0, 0);
        bn_kernel<<<CIN, 256>>>(py, px, nl_g[l], nl_beta[l]);
    }

    // 3) conv3d (im2col + K-split GEMM) -> relu -> mean = goal_pre
    im2col_kernel<<<(int)(((size_t)KCONV * PCONV) / 256), 256>>>();
    zero_kernel<<<(FFD * PCONV + 255) / 256, 256>>>(pconv, FFD * PCONV);
    sgemm<2><<<dim3((PCONV + 127) / 128, FFD / 128, KSPLIT), 256>>>(
        tp_w, KCONV, pcol, PCONV, pconv, FFD, PCONV, KCHUNK, nullptr, nullptr, 0, 0);
    goalpre_kernel<<<dim3(FFD, BB), 128>>>(tp_b);

    // 4) ConvTranspose chain
    pack_frame<<<(CIN * BT * 64) / 256, 256>>>(frame);
    pack_w1<<<(4 * FFD * CIN) / 256, 256>>>(up1_w);
    pack_w2<<<(4 * FFD * FFD) / 256, 256>>>(up2_w);
    for (int kl = 0; kl < 4; kl++) {
        int k = kl >> 1, lcol = kl & 1;
        sgemm<3><<<dim3((BT * 64) / 128, FFD / 128, 1), 256>>>(
            pw1t + (size_t)kl * FFD * CIN, CIN, pfb, BT * 64, ps1, FFD, BT * 64, CIN,
            up1_b, nullptr, k, lcol);
    }
    for (int kl = 0; kl < 4; kl++) {
        int k = kl >> 1, lcol = kl & 1;
        sgemm<4><<<dim3((BT * 256) / 128, FFD / 128, 1), 256>>>(
            pw2t + (size_t)kl * FFD * FFD, FFD, ps1, BT * 256, ps2, FFD, BT * 256, FFD,
            up2_b, nullptr, k, lcol);
    }

    // 5) spatial attention over upsampled features
    sg_softmax_kernel<<<BT, 256>>>();
    sga_kernel<<<dim3(BT, FFD / 8), 256>>>();

    // 6) heads: goal [4,128] then state [24,128]
    head_kernel<<<BB, 512>>>(pgp, og1_w, og1_b, og2_w, og2_b, out);
    head_kernel<<<BT, 512>>>(psga, os1_w, os1_b, os2_w, os2_b, out + BB * OUTD);
}

// round 6
// speedup vs baseline: 2.9681x; 2.9613x over previous
#include <cuda_runtime.h>
#include <cuda_bf16.h>
#include <cstdint>
#include <math.h>

#define CIN   1024
#define FFD   512
#define OUTD  128
#define NTOT  4096
#define KCONV 27648
#define PCONV 1568
#define BT    24
#define NS    1024

// ---------- scratch ----------
__device__ float g_x[(size_t)NTOT * CIN];
__device__ float g_y[(size_t)NTOT * CIN];
__device__ float g_v[(size_t)NTOT * FFD];
__device__ float g_col[(size_t)PCONV * KCONV];
__device__ float g_conv[(size_t)PCONV * FFD];
__device__ float g_gp[4 * FFD];
__device__ float g_fb[(size_t)(BT * 64) * CIN];
__device__ float g_w1t[4 * FFD * CIN];
__device__ float g_w2t[4 * FFD * FFD];
__device__ float g_s1[(size_t)(BT * 256) * FFD];
__device__ float g_s2[(size_t)(BT * 1024) * FFD];
__device__ float g_pe[(size_t)NS * FFD];
__device__ float g_attn[BT * NS];
__device__ float g_sga[BT * FFD];
__device__ float g_bns[2048];

// ---------- helpers ----------
__device__ __forceinline__ uint32_t smem_u32(const void* p) {
    uint32_t a;
    asm("{ .reg .u64 t; cvta.to.shared.u64 t, %1; cvt.u32.u64 %0, t; }" : "=r"(a) : "l"(p));
    return a;
}
#define LDSM4(r0, r1, r2, r3, addr) \
    asm volatile("ldmatrix.sync.aligned.m8n8.x4.shared.b16 {%0,%1,%2,%3}, [%4];" \
        : "=r"(r0), "=r"(r1), "=r"(r2), "=r"(r3) : "r"(addr))
#define MMA(c, a, b0, b1) \
    asm volatile("mma.sync.aligned.m16n8k16.row.col.f32.bf16.bf16.f32 " \
        "{%0,%1,%2,%3},{%4,%5,%6,%7},{%8,%9},{%0,%1,%2,%3};" \
        : "+f"((c)[0]), "+f"((c)[1]), "+f"((c)[2]), "+f"((c)[3]) \
        : "r"((a)[0]), "r"((a)[1]), "r"((a)[2]), "r"((a)[3]), "r"(b0), "r"(b1))

__device__ __forceinline__ uint32_t pk(float hi, float lo) {
    uint32_t r;
    asm("cvt.rn.bf16x2.f32 %0, %1, %2;" : "=r"(r) : "f"(hi), "f"(lo));
    return r;
}
// 8 consecutive floats -> 8 bf16 hi + 8 bf16 residual lo
__device__ __forceinline__ void cvt8(float4 a, float4 b, uint4& hi, uint4& lo) {
    hi.x = pk(a.y, a.x); hi.y = pk(a.w, a.z); hi.z = pk(b.y, b.x); hi.w = pk(b.w, b.z);
    lo.x = pk(a.y - __uint_as_float(hi.x & 0xffff0000u), a.x - __uint_as_float(hi.x << 16));
    lo.y = pk(a.w - __uint_as_float(hi.y & 0xffff0000u), a.z - __uint_as_float(hi.y << 16));
    lo.z = pk(b.y - __uint_as_float(hi.z & 0xffff0000u), b.x - __uint_as_float(hi.z << 16));
    lo.w = pk(b.w - __uint_as_float(hi.w & 0xffff0000u), b.z - __uint_as_float(hi.w << 16));
}
__device__ __forceinline__ uint32_t swz(uint32_t o) { return o ^ ((o >> 3) & 0x70u); }

// ========== warp-MMA bf16-split GEMM: D[pos][f] = A[pos][K] · Wt[f][K]^T ==========
// MODE 0 plain | 1 xin+relu(v+bias[f]) | 2 atomicAdd (z = K-split) | 3 up1 scatter | 4 up2 scatter
template <int MODE>
__global__ void __launch_bounds__(256) tc_gemm(
    const float* __restrict__ A, const float* __restrict__ Wt, float* __restrict__ C,
    int Mtot, int Ntot, int Kloc, int Kfull, int ldc,
    const float* __restrict__ bias, const float* __restrict__ xin)
{
    __shared__ __align__(1024) char sA[128 * 128];
    __shared__ __align__(1024) char sB[128 * 128];
    const int tid = threadIdx.x, wid = tid >> 5, lane = tid & 31;
    const int wm = wid >> 2, wn = wid & 3;      // warp 64m x 32n
    const int row0 = blockIdx.x * 128;
    const int colW = blockIdx.y * 128;
    const int z = blockIdx.z;
    const float* Wp = Wt;
    int kbase = 0;
    if (MODE == 2) kbase = z * Kloc;
    if (MODE == 3 || MODE == 4) Wp += (size_t)z * (size_t)Ntot * Kfull;

    const uint32_t aB = smem_u32(sA), bB = smem_u32(sB);
    const int S = Kloc >> 5;

    float acc[4][4][4];
#pragma unroll
    for (int i = 0; i < 4; i++)
#pragma unroll
        for (int j = 0; j < 4; j++)
#pragma unroll
            for (int e = 0; e < 4; e++) acc[i][j][e] = 0.f;

    float4 pa[2][2], pb[2][2];
    {
        const int kg = kbase;
#pragma unroll
        for (int i = 0; i < 2; i++) {
            int idx = tid + i * 256, r = idx >> 2, g = idx & 3;
            int rg = row0 + r; if (rg >= Mtot) rg = Mtot - 1;
            const float* s = A + (size_t)rg * Kfull + kg + g * 8;
            pa[i][0] = *reinterpret_cast<const float4*>(s);
            pa[i][1] = *reinterpret_cast<const float4*>(s + 4);
            const float* t = Wp + (size_t)(colW + r) * Kfull + kg + g * 8;
            pb[i][0] = *reinterpret_cast<const float4*>(t);
            pb[i][1] = *reinterpret_cast<const float4*>(t + 4);
        }
    }

    for (int s = 0; s < S; s++) {
        __syncthreads();
#pragma unroll
        for (int i = 0; i < 2; i++) {
            int idx = tid + i * 256, r = idx >> 2, g = idx & 3;
            uint4 hi, lo;
            cvt8(pa[i][0], pa[i][1], hi, lo);
            uint32_t o = swz((uint32_t)(r * 128 + g * 16));
            *reinterpret_cast<uint4*>(sA + o) = hi;
            *reinterpret_cast<uint4*>(sA + (o ^ 64u)) = lo;   // swz(x+64) == swz(x)^64
            cvt8(pb[i][0], pb[i][1], hi, lo);
            *reinterpret_cast<uint4*>(sB + o) = hi;
            *reinterpret_cast<uint4*>(sB + (o ^ 64u)) = lo;
        }
        __syncthreads();
        if (s + 1 < S) {
            const int kg = kbase + (s + 1) * 32;
#pragma unroll
            for (int i = 0; i < 2; i++) {
                int idx = tid + i * 256, r = idx >> 2, g = idx & 3;
                int rg = row0 + r; if (rg >= Mtot) rg = Mtot - 1;
                const float* sp = A + (size_t)rg * Kfull + kg + g * 8;
                pa[i][0] = *reinterpret_cast<const float4*>(sp);
                pa[i][1] = *reinterpret_cast<const float4*>(sp + 4);
                const float* t = Wp + (size_t)(colW + r) * Kfull + kg + g * 8;
                pb[i][0] = *reinterpret_cast<const float4*>(t);
                pb[i][1] = *reinterpret_cast<const float4*>(t + 4);
            }
        }
        const int q = lane >> 3, rl = lane & 7;
#pragma unroll
        for (int ks = 0; ks < 2; ks++) {
            uint32_t ah[4][4], al[4][4];
            uint32_t ao = swz((uint32_t)((wm * 64 + (q & 1) * 8 + rl) * 128 + ks * 32 + (q >> 1) * 16));
#pragma unroll
            for (int mt = 0; mt < 4; mt++) {
                uint32_t ad = aB + ao + mt * 2048;
                LDSM4(ah[mt][0], ah[mt][1], ah[mt][2], ah[mt][3], ad);
                LDSM4(al[mt][0], al[mt][1], al[mt][2], al[mt][3], ad ^ 64u);
            }
            uint32_t bo = swz((uint32_t)((wn * 32 + (q >> 1) * 8 + rl) * 128 + ks * 32 + (q & 1) * 16));
#pragma unroll
            for (int pt = 0; pt < 2; pt++) {
                uint32_t bd = bB + bo + pt * 2048;
                uint32_t bh[4], bl[4];
                LDSM4(bh[0], bh[1], bh[2], bh[3], bd);
                LDSM4(bl[0], bl[1], bl[2], bl[3], bd ^ 64u);
#pragma unroll
                for (int mt = 0; mt < 4; mt++) {
                    float* c0 = acc[mt][2 * pt];
                    MMA(c0, ah[mt], bh[0], bh[1]);
                    MMA(c0, ah[mt], bl[0], bl[1]);
                    MMA(c0, al[mt], bh[0], bh[1]);
                    float* c1 = acc[mt][2 * pt + 1];
                    MMA(c1, ah[mt], bh[2], bh[3]);
                    MMA(c1, ah[mt], bl[2], bl[3]);
                    MMA(c1, al[mt], bh[2], bh[3]);
                }
            }
        }
    }

    // epilogue
#pragma unroll
    for (int mt = 0; mt < 4; mt++) {
#pragma unroll
        for (int nt = 0; nt < 4; nt++) {
            int f = colW + wn * 32 + nt * 8 + 2 * (lane & 3);
            float b0 = 0.f, b1 = 0.f;
            if (MODE == 1 || MODE == 3 || MODE == 4) { b0 = bias[f]; b1 = bias[f + 1]; }
#pragma unroll
            for (int hh = 0; hh < 2; hh++) {
                int pos = row0 + wm * 64 + mt * 16 + (lane >> 2) + hh * 8;
                if (pos >= Mtot) continue;
                float v0 = acc[mt][nt][hh * 2], v1 = acc[mt][nt][hh * 2 + 1];
                if (MODE == 0) {
                    *reinterpret_cast<float2*>(&C[(size_t)pos * ldc + f]) = make_float2(v0, v1);
                } else if (MODE == 1) {
                    float2 xv = *reinterpret_cast<const float2*>(&xin[(size_t)pos * ldc + f]);
                    *reinterpret_cast<float2*>(&C[(size_t)pos * ldc + f]) =
                        make_float2(xv.x + fmaxf(v0 + b0, 0.f), xv.y + fmaxf(v1 + b1, 0.f));
                } else if (MODE == 2) {
                    atomicAdd(&C[(size_t)pos * ldc + f], v0);
                    atomicAdd(&C[(size_t)pos * ldc + f + 1], v1);
                } else if (MODE == 3) {
                    int bt = pos >> 6, hw = pos & 63, h = hw >> 3, w = hw & 7;
                    int orow = bt * 256 + (h * 2 + (z >> 1)) * 16 + (w * 2 + (z & 1));
                    *reinterpret_cast<float2*>(&C[(size_t)orow * ldc + f]) =
                        make_float2(fmaxf(v0 + b0, 0.f), fmaxf(v1 + b1, 0.f));
                } else {
                    int bt = pos >> 8, hw = pos & 255, h = hw >> 4, w = hw & 15;
                    int orow = bt * 1024 + (h * 2 + (z >> 1)) * 32 + (w * 2 + (z & 1));
                    *reinterpret_cast<float2*>(&C[(size_t)orow * ldc + f]) =
                        make_float2(v0 + b0, v1 + b1);
                }
            }
        }
    }
}

// ========== misc ==========
__global__ void transpose_ctx(const float* __restrict__ ctx) {
    __shared__ float t[32][33];
    int bt = blockIdx.x, c0 = blockIdx.y * 32, hw0 = blockIdx.z * 32;
    int tx = threadIdx.x, ty = threadIdx.y;
    for (int i = ty; i < 32; i += 8)
        t[i][tx] = ctx[((size_t)bt * 1024 + c0 + i) * 256 + hw0 + tx];
    __syncthreads();
    for (int i = ty; i < 32; i += 8)
        g_x[((size_t)bt * 256 + hw0 + i) * 1024 + c0 + tx] = t[tx][i];
}
__global__ void pack_frame(const float* __restrict__ fr) {
    __shared__ float t[32][33];
    int bt = blockIdx.x, c0 = blockIdx.y * 32, hw0 = blockIdx.z * 32;
    int tx = threadIdx.x, ty = threadIdx.y;
    for (int i = ty; i < 32; i += 8)
        t[i][tx] = fr[((size_t)bt * 1024 + c0 + i) * 64 + hw0 + tx];
    __syncthreads();
    for (int i = ty; i < 32; i += 8)
        g_fb[((size_t)bt * 64 + hw0 + i) * 1024 + c0 + tx] = t[tx][i];
}
__global__ void zero_kernel(float* p, int n) {
    int i = blockIdx.x * blockDim.x + threadIdx.x;
    if (i < n) p[i] = 0.f;
}
__global__ void bn_reduce(const float* __restrict__ y) {
    int c4 = threadIdx.x;
    const float4* y4 = reinterpret_cast<const float4*>(y);
    float4 s = make_float4(0, 0, 0, 0), q = make_float4(0, 0, 0, 0);
    int n0 = blockIdx.x * 64;
    for (int n = n0; n < n0 + 64; n++) {
        float4 v = y4[(size_t)n * 256 + c4];
        s.x += v.x; s.y += v.y; s.z += v.z; s.w += v.w;
        q.x += v.x * v.x; q.y += v.y * v.y; q.z += v.z * v.z; q.w += v.w * v.w;
    }
    atomicAdd(&g_bns[c4 * 4 + 0], s.x); atomicAdd(&g_bns[c4 * 4 + 1], s.y);
    atomicAdd(&g_bns[c4 * 4 + 2], s.z); atomicAdd(&g_bns[c4 * 4 + 3], s.w);
    atomicAdd(&g_bns[1024 + c4 * 4 + 0], q.x); atomicAdd(&g_bns[1024 + c4 * 4 + 1], q.y);
    atomicAdd(&g_bns[1024 + c4 * 4 + 2], q.z); atomicAdd(&g_bns[1024 + c4 * 4 + 3], q.w);
}
__global__ void bn_apply(const float* __restrict__ y, float* __restrict__ xo,
                         const float* __restrict__ gm, const float* __restrict__ bt) {
    int idx = blockIdx.x * 256 + threadIdx.x;
    int c4 = idx & 255;
    float4 v = reinterpret_cast<const float4*>(y)[idx];
    float4 s = reinterpret_cast<const float4*>(g_bns)[c4];
    float4 q = reinterpret_cast<const float4*>(g_bns + 1024)[c4];
    float4 g = reinterpret_cast<const float4*>(gm)[c4];
    float4 b = reinterpret_cast<const float4*>(bt)[c4];
    const float in = 1.f / NTOT;
    float mx = s.x * in, my = s.y * in, mz = s.z * in, mw = s.w * in;
    float4 r;
    r.x = (v.x - mx) * rsqrtf(q.x * in - mx * mx + 1e-5f) * g.x + b.x;
    r.y = (v.y - my) * rsqrtf(q.y * in - my * my + 1e-5f) * g.y + b.y;
    r.z = (v.z - mz) * rsqrtf(q.z * in - mz * mz + 1e-5f) * g.z + b.z;
    r.w = (v.w - mw) * rsqrtf(q.w * in - mw * mw + 1e-5f) * g.w + b.w;
    reinterpret_cast<float4*>(xo)[idx] = r;
}
__global__ void im2col_kernel() {  // grid (1568,4), 256 thr -> g_col[p][c*27+r]
    __shared__ float st[256 * 28];
    int p = blockIdx.x, c0 = blockIdx.y * 256;
    int b = p / 392, q = p % 392;
    int t = q / 196, rem = q % 196, h = rem / 14, w = rem % 14;
    int nb = (b * 4 + t) * 256 + h * 16 + w;
    for (int r = 0; r < 27; r++) {
        int dt = r / 9, dh = (r / 3) % 3, dw = r % 3;
        int n = nb + dt * 256 + dh * 16 + dw;
        st[threadIdx.x * 28 + r] = g_x[(size_t)n * 1024 + c0 + threadIdx.x];
    }
    __syncthreads();
    float* dst = g_col + (size_t)p * KCONV + c0 * 27;
    for (int i = 0; i < 27; i++) {
        int idx = threadIdx.x + 256 * i;
        int cl = idx / 27, r = idx - cl * 27;
        dst[idx] = st[cl * 28 + r];
    }
}
__global__ void goalpre_kernel(const float* __restrict__ tb) {
    int b = blockIdx.x, f = threadIdx.x;
    float bias = tb[f], s = 0.f;
    for (int p = b * 392; p < (b + 1) * 392; p++)
        s += fmaxf(g_conv[(size_t)p * 512 + f] + bias, 0.f);
    g_gp[b * 512 + f] = s * (1.f / 392.f);
}
__global__ void pack_w1(const float* __restrict__ w) {
    int idx = blockIdx.x * 256 + threadIdx.x;
    int c = idx & 1023, o = idx >> 10;
    float4 v = reinterpret_cast<const float4*>(w)[(size_t)c * 512 + o];
    g_w1t[           o * 1024 + c] = v.x;
    g_w1t[ 524288 +  o * 1024 + c] = v.y;
    g_w1t[1048576 +  o * 1024 + c] = v.z;
    g_w1t[1572864 +  o * 1024 + c] = v.w;
}
__global__ void pack_w2(const float* __restrict__ w) {
    int idx = blockIdx.x * 256 + threadIdx.x;
    int c = idx & 511, o = idx >> 9;
    float4 v = reinterpret_cast<const float4*>(w)[(size_t)c * 512 + o];
    g_w2t[          o * 512 + c] = v.x;
    g_w2t[262144 +  o * 512 + c] = v.y;
    g_w2t[524288 +  o * 512 + c] = v.z;
    g_w2t[786432 +  o * 512 + c] = v.w;
}
__global__ void pe_init() {
    int idx = blockIdx.x * 256 + threadIdx.x;
    int n = idx >> 9, c = idx & 511;
    float ang = (float)n * expf(-0.01798894603890390f * (float)(c & ~1));
    g_pe[idx] = (c & 1) ? cosf(ang) : sinf(ang);
}
__global__ void sg_softmax_kernel() {
    int bt = blockIdx.x, tid = threadIdx.x, b = bt / 6;
    __shared__ float gsh[512], sg[1024], red[256];
    gsh[tid] = g_gp[b * 512 + tid];
    gsh[tid + 256] = g_gp[b * 512 + tid + 256];
    __syncthreads();
    int w = tid >> 5, lane = tid & 31;
    const float4* g4 = reinterpret_cast<const float4*>(gsh);
    for (int n = w; n < 1024; n += 8) {
        const float4* r4 = reinterpret_cast<const float4*>(&g_s2[((size_t)bt * 1024 + n) * 512]);
        float acc = 0.f;
#pragma unroll
        for (int i = 0; i < 4; i++) {
            float4 v = r4[lane + 32 * i], gg = g4[lane + 32 * i];
            acc += v.x * gg.x + v.y * gg.y + v.z * gg.z + v.w * gg.w;
        }
        for (int o = 16; o > 0; o >>= 1) acc += __shfl_down_sync(0xffffffffu, acc, o);
        if (!lane) sg[n] = acc;
    }
    __syncthreads();
    float v[4];
#pragma unroll
    for (int i = 0; i < 4; i++) v[i] = sg[tid + i * 256];
    float m = fmaxf(fmaxf(v[0], v[1]), fmaxf(v[2], v[3]));
    red[tid] = m; __syncthreads();
    for (int o = 128; o > 0; o >>= 1) { if (tid < o) red[tid] = fmaxf(red[tid], red[tid + o]); __syncthreads(); }
    m = red[0]; __syncthreads();
    float s = 0.f;
#pragma unroll
    for (int i = 0; i < 4; i++) { v[i] = expf(v[i] - m); s += v[i]; }
    red[tid] = s; __syncthreads();
    for (int o = 128; o > 0; o >>= 1) { if (tid < o) red[tid] += red[tid + o]; __syncthreads(); }
    float inv = 1.f / red[0];
#pragma unroll
    for (int i = 0; i < 4; i++) g_attn[bt * 1024 + tid + i * 256] = v[i] * inv;
}
__global__ void sga_kernel() {
    int bt = blockIdx.x, n0 = blockIdx.y * 128, c2 = threadIdx.x;
    float a0 = 0.f, a1 = 0.f;
    for (int n = n0; n < n0 + 128; n++) {
        float at = g_attn[bt * 1024 + n];
        float2 s = *reinterpret_cast<const float2*>(&g_s2[((size_t)bt * 1024 + n) * 512 + c2 * 2]);
        float2 p = *reinterpret_cast<const float2*>(&g_pe[(size_t)n * 512 + c2 * 2]);
        a0 += at * (s.x + p.x); a1 += at * (s.y + p.y);
    }
    atomicAdd(&g_sga[bt * 512 + c2 * 2], a0);
    atomicAdd(&g_sga[bt * 512 + c2 * 2 + 1], a1);
}
__global__ void head_kernel(const float* __restrict__ in,
                            const float* __restrict__ W1, const float* __restrict__ b1,
                            const float* __restrict__ W2, const float* __restrict__ b2,
                            float* __restrict__ out) {
    int r = blockIdx.x, j = threadIdx.x;
    __shared__ float xin[512], t[512];
    xin[j] = in[r * 512 + j];
    __syncthreads();
    float acc = b1[j];
    const float* w = W1 + (size_t)j * 512;
    for (int k = 0; k < 512; k++) acc += xin[k] * w[k];
    t[j] = fmaxf(acc, 0.f);
    __syncthreads();
    if (j < OUTD) {
        float a2 = b2[j];
        const float* w2 = W2 + (size_t)j * 512;
        for (int k = 0; k < 512; k++) a2 += t[k] * w2[k];
        out[r * OUTD + j] = a2;
    }
}

// ---------- launch ----------
extern "C" void kernel_launch(void* const* d_in, const int* in_sizes, int n_in,
                              void* d_out, int out_size) {
    const float* ctx   = (const float*)d_in[0];
    const float* frame = (const float*)d_in[1];
    const float* nl_vw[2]   = { (const float*)d_in[4],  (const float*)d_in[11] };
    const float* nl_ow[2]   = { (const float*)d_in[5],  (const float*)d_in[12] };
    const float* nl_ob[2]   = { (const float*)d_in[6],  (const float*)d_in[13] };
    const float* nl_g[2]    = { (const float*)d_in[7],  (const float*)d_in[14] };
    const float* nl_beta[2] = { (const float*)d_in[8],  (const float*)d_in[15] };
    const float* tp_w  = (const float*)d_in[16];
    const float* tp_b  = (const float*)d_in[17];
    const float* up1_w = (const float*)d_in[18];
    const float* up1_b = (const float*)d_in[19];
    const float* up2_w = (const float*)d_in[20];
    const float* up2_b = (const float*)d_in[21];
    float* out = (float*)d_out;

    float *px, *py, *pv, *pconv, *pw1t, *pw2t, *ps1, *ps2, *pfb, *pcol, *pgp, *psga, *pbns;
    cudaGetSymbolAddress((void**)&px, g_x);
    cudaGetSymbolAddress((void**)&py, g_y);
    cudaGetSymbolAddress((void**)&pv, g_v);
    cudaGetSymbolAddress((void**)&pconv, g_conv);
    cudaGetSymbolAddress((void**)&pw1t, g_w1t);
    cudaGetSymbolAddress((void**)&pw2t, g_w2t);
    cudaGetSymbolAddress((void**)&ps1, g_s1);
    cudaGetSymbolAddress((void**)&ps2, g_s2);
    cudaGetSymbolAddress((void**)&pfb, g_fb);
    cudaGetSymbolAddress((void**)&pcol, g_col);
    cudaGetSymbolAddress((void**)&pgp, g_gp);
    cudaGetSymbolAddress((void**)&psga, g_sga);
    cudaGetSymbolAddress((void**)&pbns, g_bns);

    transpose_ctx<<<dim3(16, 32, 8), dim3(32, 8)>>>(ctx);
    pe_init<<<2048, 256>>>();
    pack_frame<<<dim3(24, 32, 2), dim3(32, 8)>>>(frame);
    pack_w1<<<2048, 256>>>(up1_w);
    pack_w2<<<1024, 256>>>(up2_w);

    for (int l = 0; l < 2; l++) {
        tc_gemm<0><<<dim3(32, 4, 1), 256>>>(
            px, nl_vw[l], pv, NTOT, 512, 1024, 1024, 512, nullptr, nullptr);
        tc_gemm<1><<<dim3(32, 8, 1), 256>>>(
            pv, nl_ow[l], py, NTOT, 1024, 512, 512, 1024, nl_ob[l], px);
        zero_kernel<<<8, 256>>>(pbns, 2048);
        bn_reduce<<<64, 256>>>(py);
        bn_apply<<<4096, 256>>>(py, px, nl_g[l], nl_beta[l]);
    }

    im2col_kernel<<<dim3(1568, 4), 256>>>();
    zero_kernel<<<(PCONV * 512 + 255) / 256, 256>>>(pconv, PCONV * 512);
    tc_gemm<2><<<dim3(13, 4, 8), 256>>>(
        pcol, tp_w, pconv, PCONV, 512, 3456, KCONV, 512, nullptr, nullptr);
    goalpre_kernel<<<4, 512>>>(tp_b);

    tc_gemm<3><<<dim3(12, 4, 4), 256>>>(
        pfb, pw1t, ps1, 1536, 512, 1024, 1024, 512, up1_b, nullptr);
    tc_gemm<4><<<dim3(48, 4, 4), 256>>>(
        ps1, pw2t, ps2, 6144, 512, 512, 512, 512, up2_b, nullptr);

    sg_softmax_kernel<<<24, 256>>>();
    zero_kernel<<<48, 256>>>(psga, BT * 512);
    sga_kernel<<<dim3(24, 8), 256>>>();

    head_kernel<<<4, 512>>>(pgp, (const float*)d_in[22], (const float*)d_in[23],
                            (const float*)d_in[24], (const float*)d_in[25], out);
    head_kernel<<<BT, 512>>>(psga, (const float*)d_in[26], (const float*)d_in[27],
                             (const float*)d_in[28], (const float*)d_in[29], out + 4 * OUTD);
}